// round 15
// baseline (speedup 1.0000x reference)
#include <cuda_runtime.h>
#include <cooperative_groups.h>
#include <math.h>

namespace cg = cooperative_groups;

// Shapes
#define B_   32
#define N_   4096
#define C_   128
#define D_   64
#define K_   8
#define H_   128
#define BN_  (B_*N_)          // 131072
#define SLOTS_ (B_*K_)        // 256

// Scratch (device globals; no allocation allowed)
__device__ float g_kT[B_*D_*N_];   // transposed k: [b][d][j]
__device__ float g_v[BN_*D_];
__device__ float g_q[SLOTS_*D_];
__device__ float g_upd[SLOTS_*D_];
__device__ float g_sums[SLOTS_];
__device__ float g_slot[SLOTS_*D_];
__device__ float g_wT[4][192*64];
__device__ int   g_qready[B_];
__device__ int   g_done[B_][3];

// ---- packed f32x2 helpers (Blackwell FFMA2) --------------------------------
__device__ __forceinline__ unsigned long long pack2(float x) {
    unsigned long long r;
    unsigned xi = __float_as_uint(x);
    asm("mov.b64 %0, {%1, %1};" : "=l"(r) : "r"(xi));
    return r;
}
__device__ __forceinline__ unsigned long long packab(float lo, float hi) {
    unsigned long long r;
    asm("mov.b64 %0, {%1, %2};" : "=l"(r)
        : "r"(__float_as_uint(lo)), "r"(__float_as_uint(hi)));
    return r;
}
__device__ __forceinline__ unsigned long long fma2(unsigned long long a,
                                                   unsigned long long b,
                                                   unsigned long long c) {
    unsigned long long d;
    asm("fma.rn.f32x2 %0, %1, %2, %3;" : "=l"(d) : "l"(a), "l"(b), "l"(c));
    return d;
}
__device__ __forceinline__ float2 unpack2(unsigned long long v) {
    unsigned lo, hi;
    asm("mov.b64 {%0, %1}, %2;" : "=r"(lo), "=r"(hi) : "l"(v));
    float2 f; f.x = __uint_as_float(lo); f.y = __uint_as_float(hi);
    return f;
}

// ---------------------------------------------------------------------------
// Kernel A (R13 known-good): x = LN(feat); kT via SMEM stage; v = x@Wv
// ---------------------------------------------------------------------------
#define KS_ 68
__global__ void ln_kv_kernel(const float* __restrict__ feat,
                             const float* __restrict__ gamma,
                             const float* __restrict__ beta,
                             const float* __restrict__ Wk,
                             const float* __restrict__ Wv) {
    extern __shared__ float sm[];
    float* Wc = sm;                 // 128*128
    float* xs = sm + 128*128;       // 64*128

    const int tid  = threadIdx.x;
    const int lane = tid & 31;
    const int warp = tid >> 5;

    for (int idx = tid; idx < 128*64; idx += 256) {
        int c = idx >> 6, d = idx & 63;
        Wc[c*128 + d]      = Wk[idx];
        Wc[c*128 + 64 + d] = Wv[idx];
    }
    const float4 gg = ((const float4*)gamma)[lane];
    const float4 bb = ((const float4*)beta)[lane];
    __syncthreads();

    for (int chunk = blockIdx.x; chunk < BN_/64; chunk += gridDim.x) {
        const int row0 = chunk * 64;
        #pragma unroll
        for (int rr = 0; rr < 8; rr++) {
            int rl = warp*8 + rr;
            float4 xv = ((const float4*)(feat + (size_t)(row0+rl)*128))[lane];
            float s  = xv.x+xv.y+xv.z+xv.w;
            float s2 = xv.x*xv.x + xv.y*xv.y + xv.z*xv.z + xv.w*xv.w;
            #pragma unroll
            for (int o = 16; o > 0; o >>= 1) {
                s  += __shfl_xor_sync(0xffffffffu, s,  o);
                s2 += __shfl_xor_sync(0xffffffffu, s2, o);
            }
            float mean = s * (1.f/128.f);
            float var  = s2 * (1.f/128.f) - mean*mean;
            float rstd = rsqrtf(var + 1e-5f);
            float4 xn;
            xn.x = (xv.x-mean)*rstd*gg.x + bb.x;
            xn.y = (xv.y-mean)*rstd*gg.y + bb.y;
            xn.z = (xv.z-mean)*rstd*gg.z + bb.z;
            xn.w = (xv.w-mean)*rstd*gg.w + bb.w;
            ((float4*)(xs + rl*128))[lane] = xn;
        }
        __syncthreads();

        unsigned long long acc2[8][2];
        #pragma unroll
        for (int ri = 0; ri < 8; ri++) { acc2[ri][0] = 0ULL; acc2[ri][1] = 0ULL; }

        #pragma unroll 2
        for (int c4 = 0; c4 < 32; c4++) {
            float4 xr[8];
            #pragma unroll
            for (int ri = 0; ri < 8; ri++)
                xr[ri] = ((const float4*)(xs + (warp*8+ri)*128))[c4];
            #pragma unroll
            for (int cc = 0; cc < 4; cc++) {
                int c = c4*4 + cc;
                double2 wd = ((const double2*)(Wc + c*128))[lane];
                unsigned long long w01 = __double_as_longlong(wd.x);
                unsigned long long w23 = __double_as_longlong(wd.y);
                #pragma unroll
                for (int ri = 0; ri < 8; ri++) {
                    float xv = (cc == 0) ? xr[ri].x : (cc == 1) ? xr[ri].y
                             : (cc == 2) ? xr[ri].z : xr[ri].w;
                    unsigned long long xx = pack2(xv);
                    acc2[ri][0] = fma2(xx, w01, acc2[ri][0]);
                    acc2[ri][1] = fma2(xx, w23, acc2[ri][1]);
                }
            }
        }
        __syncthreads();

        float* kstage = xs;
        float val[8][4];
        #pragma unroll
        for (int ri = 0; ri < 8; ri++) {
            float2 a0 = unpack2(acc2[ri][0]);
            float2 a1 = unpack2(acc2[ri][1]);
            val[ri][0] = a0.x; val[ri][1] = a0.y;
            val[ri][2] = a1.x; val[ri][3] = a1.y;
        }
        if (lane < 16) {
            const int jl0 = warp*8;
            #pragma unroll
            for (int cc = 0; cc < 4; cc++) {
                int col = 4*lane + cc;
                float* dst = kstage + col*KS_ + jl0;
                *(float4*)(dst)     = make_float4(val[0][cc], val[1][cc],
                                                  val[2][cc], val[3][cc]);
                *(float4*)(dst + 4) = make_float4(val[4][cc], val[5][cc],
                                                  val[6][cc], val[7][cc]);
            }
        } else {
            #pragma unroll
            for (int ri = 0; ri < 8; ri++) {
                size_t row = (size_t)(row0 + warp*8 + ri);
                ((float4*)(g_v + row*64))[lane - 16] =
                    make_float4(val[ri][0], val[ri][1], val[ri][2], val[ri][3]);
            }
        }
        __syncthreads();

        {
            const size_t bb2 = (size_t)(row0 >> 12);
            const int jj0 = row0 & 4095;
            #pragma unroll 4
            for (int idx = tid; idx < 4096; idx += 256) {
                int col = idx >> 6, j = idx & 63;
                g_kT[(bb2*64 + col)*4096 + jj0 + j] = kstage[col*KS_ + j];
            }
        }
        __syncthreads();
    }
}

// ---------------------------------------------------------------------------
// FUSED dataflow kernel: per-batch flags instead of grid-wide barriers.
// grid 512 x 256 cooperative (co-residency). Block (b = bid>>4, jb = bid&15).
// The 16th attn block of (b, it) performs the 8-row update for batch b.
// ---------------------------------------------------------------------------
__global__ void __launch_bounds__(256, 4)
fused_iter_kernel(
    const float* __restrict__ slot,
    const float* __restrict__ qg,   const float* __restrict__ qb,
    const float* __restrict__ Wq,
    const float* __restrict__ qbgg, const float* __restrict__ qbgb,
    const float* __restrict__ Wqbg,
    const float* __restrict__ gwih, const float* __restrict__ gwhh,
    const float* __restrict__ gbih, const float* __restrict__ gbhh,
    const float* __restrict__ bgwih, const float* __restrict__ bgwhh,
    const float* __restrict__ bgbih, const float* __restrict__ bgbhh,
    const float* __restrict__ rlng, const float* __restrict__ rlnb,
    const float* __restrict__ rw1,  const float* __restrict__ rb1,
    const float* __restrict__ rw2,  const float* __restrict__ rb2,
    const float* __restrict__ bglng, const float* __restrict__ bglnb,
    const float* __restrict__ bgw1,  const float* __restrict__ bgb1,
    const float* __restrict__ bgw2,  const float* __restrict__ bgb2,
    float* __restrict__ out_slots,
    float* __restrict__ out_attn) {
    cg::grid_group grid = cg::this_grid();
    const int bid = blockIdx.x;
    const int t   = threadIdx.x;
    const int b   = bid >> 4;
    const int j0  = (bid & 15) * 256;

    __shared__ float ash[8][256];
    __shared__ unsigned long long qp[4][64];
    __shared__ float xn[64];
    __shared__ float ps[4], ps2[4];
    // update workspace (2 rows at a time)
    __shared__ float uvec[2][2][64], ussh[2][64], ugsh[2][6][64];
    __shared__ float uxn[2][64], uhb[2][128], upo[2][2][64];
    __shared__ float ups[2][2], ups2[2][2];
    __shared__ int swin;

    // ================= pre-loop =================
    if (bid < 256) {
        const int r = bid;
        const bool bgr = (r & 7) == 0;
        if ((r & 7) == 0 && t == 0) {            // zero flags (graph-replay safe)
            int bb = r >> 3;
            g_qready[bb] = 0;
            g_done[bb][0] = 0; g_done[bb][1] = 0; g_done[bb][2] = 0;
        }
        float x = 0.f;
        if (t < 64) {
            x = slot[r*64 + t];
            float s = x, s2 = x*x;
            #pragma unroll
            for (int o = 16; o > 0; o >>= 1) {
                s  += __shfl_xor_sync(0xffffffffu, s,  o);
                s2 += __shfl_xor_sync(0xffffffffu, s2, o);
            }
            if ((t & 31) == 0) { ps[t>>5] = s; ps2[t>>5] = s2; }
        }
        __syncthreads();
        if (t < 64) {
            const float* g  = bgr ? qbgg : qg;
            const float* bt = bgr ? qbgb : qb;
            float s = ps[0] + ps[1], s2 = ps2[0] + ps2[1];
            float mean = s * (1.f/64.f);
            float var  = s2 * (1.f/64.f) - mean*mean;
            float rstd = rsqrtf(var + 1e-5f);
            xn[t] = (x - mean)*rstd*g[t] + bt[t];
        }
        __syncthreads();
        if (t < 64) {
            const float* W = bgr ? Wqbg : Wq;
            float a0 = 0.f, a1 = 0.f;
            #pragma unroll 8
            for (int c = 0; c < 64; c += 2) {
                a0 += xn[c]  *__ldg(W + c*64 + t);
                a1 += xn[c+1]*__ldg(W + (c+1)*64 + t);
            }
            g_q[r*64 + t] = (a0 + a1) * 0.125f;
            g_upd[r*64 + t] = 0.f;
        }
        if (t == 0) g_sums[r] = 0.f;
    } else if (bid < 268) {
        const int m = (bid - 256) / 3;
        const int p = (bid - 256) % 3;
        const float* src = (m == 0) ? gwih : (m == 1) ? gwhh
                         : (m == 2) ? bgwih : bgwhh;
        for (int i = t; i < 4096; i += 256) {
            int rr = i >> 6, cc = i & 63;
            g_wT[m][(p*64 + cc)*64 + rr] = src[(p*64 + rr)*64 + cc];
        }
    }

    grid.sync();   // the ONLY grid-wide barrier

    // ================= dataflow iteration loop =================
    for (int it = 0; it < 3; it++) {
        // ---- wait for this batch's q (level flag) ----
        if (it > 0) {
            if (t == 0) {
                while (*(volatile int*)&g_qready[b] < it) __nanosleep(64);
            }
            __syncthreads();
            __threadfence();    // CCTL.IVALL: drop stale L1 lines (g_q, g_slot...)
        }

        // ---------------- attn ----------------
        {
            int p = t >> 6, c = t & 63;
            float lo = g_q[b*512 + (2*p)*64 + c];
            float hi = g_q[b*512 + (2*p+1)*64 + c];
            qp[p][c] = packab(lo, hi);
        }
        __syncthreads();

        const float* kTb = g_kT + (size_t)(b*64)*4096 + j0 + t;
        unsigned long long dp[4] = {0ULL, 0ULL, 0ULL, 0ULL};
        #pragma unroll 8
        for (int c = 0; c < 64; c++) {
            unsigned long long kc = pack2(__ldg(kTb + (size_t)c*4096));
            dp[0] = fma2(kc, qp[0][c], dp[0]);
            dp[1] = fma2(kc, qp[1][c], dp[1]);
            dp[2] = fma2(kc, qp[2][c], dp[2]);
            dp[3] = fma2(kc, qp[3][c], dp[3]);
        }
        float dots[8];
        #pragma unroll
        for (int p = 0; p < 4; p++) {
            float2 d2 = unpack2(dp[p]);
            dots[2*p]   = d2.x;
            dots[2*p+1] = d2.y;
        }
        float mx = -1e30f;
        #pragma unroll
        for (int i = 0; i < 8; i++) mx = fmaxf(mx, dots[i]);
        float e[8], se = 0.f;
        #pragma unroll
        for (int i = 0; i < 8; i++) { e[i] = __expf(dots[i] - mx); se += e[i]; }
        float inv = 1.f / se;
        #pragma unroll
        for (int i = 0; i < 8; i++) {
            float a = e[i]*inv + 1e-8f;
            ash[i][t] = a;
            if (it == 2)
                out_attn[((size_t)(b*8 + i))*N_ + j0 + t] = a;
        }
        __syncthreads();

        {
            int w = t >> 5, lane = t & 31;
            float s = 0.f;
            #pragma unroll
            for (int q8 = 0; q8 < 8; q8++) s += ash[w][lane + 32*q8];
            #pragma unroll
            for (int o = 16; o > 0; o >>= 1)
                s += __shfl_xor_sync(0xffffffffu, s, o);
            if (lane == 0) atomicAdd(&g_sums[b*8 + w], s);
        }

        // phase 2: v read once per block (R14 mapping)
        {
            const int d4   = t & 15;
            const int quad = (t >> 4) & 1;
            const int jw   = (t >> 5) * 32;
            float4 up0 = make_float4(0.f,0.f,0.f,0.f);
            float4 up1 = up0, up2 = up0, up3 = up0;
            const float4* vp =
                (const float4*)(g_v + ((size_t)b*N_ + j0 + jw)*64);
            const float* a0p = &ash[quad*4 + 0][jw];
            const float* a1p = &ash[quad*4 + 1][jw];
            const float* a2p = &ash[quad*4 + 2][jw];
            const float* a3p = &ash[quad*4 + 3][jw];
            #pragma unroll 4
            for (int j = 0; j < 32; j++) {
                float4 vv = __ldg(vp + j*16 + d4);
                float a0 = a0p[j], a1 = a1p[j], a2 = a2p[j], a3 = a3p[j];
                up0.x += a0*vv.x; up0.y += a0*vv.y;
                up0.z += a0*vv.z; up0.w += a0*vv.w;
                up1.x += a1*vv.x; up1.y += a1*vv.y;
                up1.z += a1*vv.z; up1.w += a1*vv.w;
                up2.x += a2*vv.x; up2.y += a2*vv.y;
                up2.z += a2*vv.z; up2.w += a2*vv.w;
                up3.x += a3*vv.x; up3.y += a3*vv.y;
                up3.z += a3*vv.z; up3.w += a3*vv.w;
            }
            float* ub = &g_upd[((size_t)(b*8) + quad*4)*64 + d4*4];
            atomicAdd(ub+0,      up0.x); atomicAdd(ub+1,      up0.y);
            atomicAdd(ub+2,      up0.z); atomicAdd(ub+3,      up0.w);
            atomicAdd(ub+64+0,   up1.x); atomicAdd(ub+64+1,   up1.y);
            atomicAdd(ub+64+2,   up1.z); atomicAdd(ub+64+3,   up1.w);
            atomicAdd(ub+128+0,  up2.x); atomicAdd(ub+128+1,  up2.y);
            atomicAdd(ub+128+2,  up2.z); atomicAdd(ub+128+3,  up2.w);
            atomicAdd(ub+192+0,  up3.x); atomicAdd(ub+192+1,  up3.y);
            atomicAdd(ub+192+2,  up3.z); atomicAdd(ub+192+3,  up3.w);
        }

        // ---- arrival counter; 16th arriver becomes the update block ----
        __threadfence();          // make my g_upd/g_sums atomics visible
        __syncthreads();
        if (t == 0) swin = (atomicAdd(&g_done[b][it], 1) == 15) ? 1 : 0;
        __syncthreads();
        if (!swin) continue;      // block-uniform branch

        __threadfence();          // see all 16 blocks' contributions

        // ---------------- update: 8 rows of batch b, 2 per pass ----------------
        const float* sp = (it == 0) ? slot : (const float*)g_slot;
        #pragma unroll 1
        for (int rr = 0; rr < 4; rr++) {
            const int ro  = t >> 7;          // row within pair
            const int tl  = t & 127;
            const int half = tl >> 6;
            const int u   = tl & 63;
            const int r   = b*8 + rr*2 + ro;
            const bool bgr = (rr == 0 && ro == 0);

            if (half == 0) uvec[ro][0][u] = g_upd[r*64 + u] / g_sums[r];
            else           uvec[ro][1][u] = sp[r*64 + u];
            __syncthreads();

            {
                const float* wT   = (half == 0) ? (bgr ? g_wT[2] : g_wT[0])
                                                : (bgr ? g_wT[3] : g_wT[1]);
                const float* bias = (half == 0) ? (bgr ? bgbih : gbih)
                                                : (bgr ? bgbhh : gbhh);
                const float* vec  = uvec[ro][half];
                #pragma unroll
                for (int p = 0; p < 3; p++) {
                    const float* wp = wT + (size_t)(p*64)*64 + u;
                    float a0 = 0.f, a1 = 0.f, a2 = 0.f, a3 = 0.f;
                    #pragma unroll
                    for (int c = 0; c < 64; c += 4) {
                        a0 += vec[c]  *__ldg(wp + (size_t)(c  )*64);
                        a1 += vec[c+1]*__ldg(wp + (size_t)(c+1)*64);
                        a2 += vec[c+2]*__ldg(wp + (size_t)(c+2)*64);
                        a3 += vec[c+3]*__ldg(wp + (size_t)(c+3)*64);
                    }
                    ugsh[ro][half*3 + p][u] = (a0 + a1) + (a2 + a3)
                                             + bias[p*64 + u];
                }
            }
            __syncthreads();

            float s = 0.f;
            if (tl < 64) {
                float hval = uvec[ro][1][u];
                float rg = 1.f/(1.f + __expf(-(ugsh[ro][0][u] + ugsh[ro][3][u])));
                float z  = 1.f/(1.f + __expf(-(ugsh[ro][1][u] + ugsh[ro][4][u])));
                float n  = tanhf(ugsh[ro][2][u] + rg*ugsh[ro][5][u]);
                s = (1.f - z)*n + z*hval;
                ussh[ro][u] = s;
                float a = s, a2v = s*s;
                #pragma unroll
                for (int o = 16; o > 0; o >>= 1) {
                    a   += __shfl_xor_sync(0xffffffffu, a,   o);
                    a2v += __shfl_xor_sync(0xffffffffu, a2v, o);
                }
                if ((tl & 31) == 0) { ups[ro][tl>>5] = a; ups2[ro][tl>>5] = a2v; }
            }
            __syncthreads();
            if (tl < 64) {
                const float* lng = bgr ? bglng : rlng;
                const float* lnb = bgr ? bglnb : rlnb;
                float tot = ups[ro][0] + ups[ro][1];
                float tot2 = ups2[ro][0] + ups2[ro][1];
                float mean = tot * (1.f/64.f);
                float var  = tot2 * (1.f/64.f) - mean*mean;
                float rstd = rsqrtf(var + 1e-5f);
                uxn[ro][u] = (s - mean)*rstd*lng[u] + lnb[u];
            }
            __syncthreads();

            {
                const float* w1 = bgr ? bgw1 : rw1;
                const float* b1 = bgr ? bgb1 : rb1;
                float h0 = b1[tl], h1 = 0.f, h2 = 0.f, h3 = 0.f;
                #pragma unroll
                for (int c = 0; c < 64; c += 4) {
                    h0 += uxn[ro][c]  *__ldg(w1 + (c  )*128 + tl);
                    h1 += uxn[ro][c+1]*__ldg(w1 + (c+1)*128 + tl);
                    h2 += uxn[ro][c+2]*__ldg(w1 + (c+2)*128 + tl);
                    h3 += uxn[ro][c+3]*__ldg(w1 + (c+3)*128 + tl);
                }
                uhb[ro][tl] = fmaxf((h0 + h1) + (h2 + h3), 0.f);
            }
            __syncthreads();

            {
                const float* w2 = bgr ? bgw2 : rw2;
                float o0 = 0.f, o1 = 0.f, o2 = 0.f, o3 = 0.f;
                const int hh0 = half * 64;
                #pragma unroll
                for (int hh = 0; hh < 64; hh += 4) {
                    o0 += uhb[ro][hh0+hh]  *__ldg(w2 + (hh0+hh  )*64 + u);
                    o1 += uhb[ro][hh0+hh+1]*__ldg(w2 + (hh0+hh+1)*64 + u);
                    o2 += uhb[ro][hh0+hh+2]*__ldg(w2 + (hh0+hh+2)*64 + u);
                    o3 += uhb[ro][hh0+hh+3]*__ldg(w2 + (hh0+hh+3)*64 + u);
                }
                upo[ro][half][u] = (o0 + o1) + (o2 + o3);
            }
            __syncthreads();

            float o = 0.f;
            if (tl < 64) {
                const float* b2 = bgr ? bgb2 : rb2;
                o = ussh[ro][u] + b2[u] + upo[ro][0][u] + upo[ro][1][u];
                g_slot[r*64 + u] = o;
                if (it == 2) out_slots[r*64 + u] = o;
            }

            if (it < 2) {
                if (tl < 64) {
                    float a = o, a2v = o*o;
                    #pragma unroll
                    for (int off = 16; off > 0; off >>= 1) {
                        a   += __shfl_xor_sync(0xffffffffu, a,   off);
                        a2v += __shfl_xor_sync(0xffffffffu, a2v, off);
                    }
                    if ((tl & 31) == 0) { ups[ro][tl>>5] = a; ups2[ro][tl>>5] = a2v; }
                }
                __syncthreads();
                if (tl < 64) {
                    const float* qgp = bgr ? qbgg : qg;
                    const float* qbp = bgr ? qbgb : qb;
                    float tot = ups[ro][0] + ups[ro][1];
                    float tot2 = ups2[ro][0] + ups2[ro][1];
                    float mean = tot * (1.f/64.f);
                    float var  = tot2 * (1.f/64.f) - mean*mean;
                    float rstd = rsqrtf(var + 1e-5f);
                    uxn[ro][u] = (o - mean)*rstd*qgp[u] + qbp[u];
                }
                __syncthreads();
                {
                    const float* Wp = bgr ? Wqbg : Wq;
                    const int c0 = half * 32;
                    float q0 = 0.f, q1 = 0.f;
                    #pragma unroll
                    for (int c = 0; c < 32; c += 2) {
                        q0 += uxn[ro][c0+c]  *__ldg(Wp + (c0+c  )*64 + u);
                        q1 += uxn[ro][c0+c+1]*__ldg(Wp + (c0+c+1)*64 + u);
                    }
                    upo[ro][half][u] = q0 + q1;
                }
                __syncthreads();
                if (tl < 64) {
                    if (half == 0) {
                        g_q[r*64 + u] = (upo[ro][0][u] + upo[ro][1][u]) * 0.125f;
                        g_upd[r*64 + u] = 0.f;
                    }
                }
                if (tl == 0) g_sums[r] = 0.f;
            }
            __syncthreads();
        }

        // ---- release next iteration for this batch ----
        if (it < 2) {
            __threadfence();
            __syncthreads();
            if (t == 0) atomicExch(&g_qready[b], it + 1);
        }
    }
}

// ---------------------------------------------------------------------------
extern "C" void kernel_launch(void* const* d_in, const int* in_sizes, int n_in,
                              void* d_out, int out_size) {
    const float* feat   = (const float*)d_in[0];
    const float* slot   = (const float*)d_in[1];
    const float* nfg    = (const float*)d_in[2];
    const float* nfb    = (const float*)d_in[3];
    const float* Wk     = (const float*)d_in[4];
    const float* Wv     = (const float*)d_in[5];
    const float* qg     = (const float*)d_in[6];
    const float* qb     = (const float*)d_in[7];
    const float* Wq     = (const float*)d_in[8];
    const float* qbgg   = (const float*)d_in[9];
    const float* qbgb   = (const float*)d_in[10];
    const float* Wqbg   = (const float*)d_in[11];
    const float* gwih   = (const float*)d_in[12];
    const float* gwhh   = (const float*)d_in[13];
    const float* gbih   = (const float*)d_in[14];
    const float* gbhh   = (const float*)d_in[15];
    const float* bgwih  = (const float*)d_in[16];
    const float* bgwhh  = (const float*)d_in[17];
    const float* bgbih  = (const float*)d_in[18];
    const float* bgbhh  = (const float*)d_in[19];
    const float* rlng   = (const float*)d_in[20];
    const float* rlnb   = (const float*)d_in[21];
    const float* rw1    = (const float*)d_in[22];
    const float* rb1    = (const float*)d_in[23];
    const float* rw2    = (const float*)d_in[24];
    const float* rb2    = (const float*)d_in[25];
    const float* bglng  = (const float*)d_in[26];
    const float* bglnb  = (const float*)d_in[27];
    const float* bgw1   = (const float*)d_in[28];
    const float* bgb1   = (const float*)d_in[29];
    const float* bgw2   = (const float*)d_in[30];
    const float* bgb2   = (const float*)d_in[31];

    float* out       = (float*)d_out;
    float* out_attn  = out + SLOTS_*D_;   // slots first, then attn

    const int smem_lnkv = (128*128 + 64*128) * (int)sizeof(float);  // 98304 B
    cudaFuncSetAttribute(ln_kv_kernel,
                         cudaFuncAttributeMaxDynamicSharedMemorySize, smem_lnkv);

    ln_kv_kernel<<<296, 256, smem_lnkv>>>(feat, nfg, nfb, Wk, Wv);

    void* args[] = {
        (void*)&slot,
        (void*)&qg,   (void*)&qb,   (void*)&Wq,
        (void*)&qbgg, (void*)&qbgb, (void*)&Wqbg,
        (void*)&gwih, (void*)&gwhh, (void*)&gbih, (void*)&gbhh,
        (void*)&bgwih, (void*)&bgwhh, (void*)&bgbih, (void*)&bgbhh,
        (void*)&rlng, (void*)&rlnb, (void*)&rw1, (void*)&rb1,
        (void*)&rw2,  (void*)&rb2,
        (void*)&bglng, (void*)&bglnb, (void*)&bgw1, (void*)&bgb1,
        (void*)&bgw2,  (void*)&bgb2,
        (void*)&out, (void*)&out_attn
    };
    cudaLaunchCooperativeKernel((const void*)fused_iter_kernel,
                                dim3(512), dim3(256), args, 0, (cudaStream_t)0);
}

// round 16
// speedup vs baseline: 1.5295x; 1.5295x over previous
#include <cuda_runtime.h>
#include <cooperative_groups.h>
#include <cuda_bf16.h>
#include <math.h>

namespace cg = cooperative_groups;

// Shapes
#define B_   32
#define N_   4096
#define C_   128
#define D_   64
#define K_   8
#define H_   128
#define BN_  (B_*N_)          // 131072
#define SLOTS_ (B_*K_)        // 256

// Scratch (device globals; no allocation allowed)
__device__ float g_kT[B_*D_*N_];   // transposed k: [b][d][j]
__device__ float g_v[BN_*D_];
__device__ float g_q[SLOTS_*D_];
__device__ float g_upd[SLOTS_*D_];
__device__ float g_sums[SLOTS_];
__device__ float g_slot[SLOTS_*D_];
__device__ float g_wT[4][192*64];

// ---- packed f32x2 helpers (Blackwell FFMA2) --------------------------------
__device__ __forceinline__ unsigned long long pack2(float x) {
    unsigned long long r;
    unsigned xi = __float_as_uint(x);
    asm("mov.b64 %0, {%1, %1};" : "=l"(r) : "r"(xi));
    return r;
}
__device__ __forceinline__ unsigned long long packab(float lo, float hi) {
    unsigned long long r;
    asm("mov.b64 %0, {%1, %2};" : "=l"(r)
        : "r"(__float_as_uint(lo)), "r"(__float_as_uint(hi)));
    return r;
}
__device__ __forceinline__ unsigned long long fma2(unsigned long long a,
                                                   unsigned long long b,
                                                   unsigned long long c) {
    unsigned long long d;
    asm("fma.rn.f32x2 %0, %1, %2, %3;" : "=l"(d) : "l"(a), "l"(b), "l"(c));
    return d;
}
__device__ __forceinline__ float2 unpack2(unsigned long long v) {
    unsigned lo, hi;
    asm("mov.b64 {%0, %1}, %2;" : "=r"(lo), "=r"(hi) : "l"(v));
    float2 f; f.x = __uint_as_float(lo); f.y = __uint_as_float(hi);
    return f;
}

// ---- mma.sync bf16 helper (sm_80+ path; compiles for sm_103) ---------------
__device__ __forceinline__ void mma16816(float c[4],
                                         unsigned a0, unsigned a1,
                                         unsigned a2, unsigned a3,
                                         unsigned b0, unsigned b1) {
    asm volatile(
        "mma.sync.aligned.m16n8k16.row.col.f32.bf16.bf16.f32 "
        "{%0,%1,%2,%3}, {%4,%5,%6,%7}, {%8,%9}, {%0,%1,%2,%3};"
        : "+f"(c[0]), "+f"(c[1]), "+f"(c[2]), "+f"(c[3])
        : "r"(a0), "r"(a1), "r"(a2), "r"(a3), "r"(b0), "r"(b1));
}
__device__ __forceinline__ unsigned bpack(__nv_bfloat16 a, __nv_bfloat16 b) {
    return ((unsigned)__bfloat16_as_ushort(b) << 16) | __bfloat16_as_ushort(a);
}

// ---------------------------------------------------------------------------
// Kernel A (tensor-core): x = LN(feat); [k|v] = x @ [Wk|Wv] via bf16-split
// mma.sync (D = xhi@Whi + xhi@Wlo + xlo@Whi, fp32 accum).
// 64-row tiles; 256 threads; warp (w&3) = 16 rows, (w>>2) = k/v half.
// SMEM (104448B, 2 CTA/SM): xhi|xlo (34816B, reused as staging) + WThi|WTlo.
// ---------------------------------------------------------------------------
#define XS_ 136   // bf16 row stride (272B): conflict-free fragment LDS
__global__ void __launch_bounds__(256)
ln_kv_kernel(const float* __restrict__ feat,
             const float* __restrict__ gamma,
             const float* __restrict__ beta,
             const float* __restrict__ Wk,
             const float* __restrict__ Wv) {
    extern __shared__ char smraw[];
    __nv_bfloat16* xhi  = (__nv_bfloat16*)smraw;            // 64 x XS_
    __nv_bfloat16* xlo  = xhi + 64*XS_;
    __nv_bfloat16* WThi = xlo + 64*XS_;                     // 128 outs x XS_
    __nv_bfloat16* WTlo = WThi + 128*XS_;
    float* kstage = (float*)smraw;                          // reuse x region
    float* vstage = kstage + 64*68;                         // word 4352

    const int tid  = threadIdx.x;
    const int lane = tid & 31;
    const int warp = tid >> 5;

    // one-time W staging: WT[out][c], bf16 hi/lo (outs 0-63 = k, 64-127 = v)
    for (int idx = tid; idx < 128*64; idx += 256) {
        int c = idx >> 6, o = idx & 63;
        float wk = Wk[idx], wv = Wv[idx];
        __nv_bfloat16 h = __float2bfloat16(wk);
        WThi[o*XS_ + c] = h;
        WTlo[o*XS_ + c] = __float2bfloat16(wk - __bfloat162float(h));
        h = __float2bfloat16(wv);
        WThi[(64 + o)*XS_ + c] = h;
        WTlo[(64 + o)*XS_ + c] = __float2bfloat16(wv - __bfloat162float(h));
    }
    const float4 gg = ((const float4*)gamma)[lane];
    const float4 bb = ((const float4*)beta)[lane];
    __syncthreads();

    const int r0 = (warp & 3) * 16;   // fragment row base
    const int ch = warp >> 2;         // 0: k outs, 1: v outs
    const int fr = lane >> 2;         // 0..7
    const int fc = (lane & 3) * 2;    // k-pair offset

    for (int chunk = blockIdx.x; chunk < BN_/64; chunk += gridDim.x) {
        const int row0 = chunk * 64;
        // ---- LN phase: warp w rows w*8..w*8+7; bf16 hi/lo split stores ----
        #pragma unroll
        for (int rr = 0; rr < 8; rr++) {
            int rl = warp*8 + rr;
            float4 xv = ((const float4*)(feat + (size_t)(row0+rl)*128))[lane];
            float s  = xv.x+xv.y+xv.z+xv.w;
            float s2 = xv.x*xv.x + xv.y*xv.y + xv.z*xv.z + xv.w*xv.w;
            #pragma unroll
            for (int o = 16; o > 0; o >>= 1) {
                s  += __shfl_xor_sync(0xffffffffu, s,  o);
                s2 += __shfl_xor_sync(0xffffffffu, s2, o);
            }
            float mean = s * (1.f/128.f);
            float var  = s2 * (1.f/128.f) - mean*mean;
            float rstd = rsqrtf(var + 1e-5f);
            float x0 = (xv.x-mean)*rstd*gg.x + bb.x;
            float x1 = (xv.y-mean)*rstd*gg.y + bb.y;
            float x2 = (xv.z-mean)*rstd*gg.z + bb.z;
            float x3 = (xv.w-mean)*rstd*gg.w + bb.w;
            __nv_bfloat16 h0 = __float2bfloat16(x0);
            __nv_bfloat16 h1 = __float2bfloat16(x1);
            __nv_bfloat16 h2 = __float2bfloat16(x2);
            __nv_bfloat16 h3 = __float2bfloat16(x3);
            __nv_bfloat16 l0 = __float2bfloat16(x0 - __bfloat162float(h0));
            __nv_bfloat16 l1 = __float2bfloat16(x1 - __bfloat162float(h1));
            __nv_bfloat16 l2 = __float2bfloat16(x2 - __bfloat162float(h2));
            __nv_bfloat16 l3 = __float2bfloat16(x3 - __bfloat162float(h3));
            unsigned* hp = (unsigned*)(xhi + rl*XS_);
            unsigned* lp = (unsigned*)(xlo + rl*XS_);
            hp[lane*2]     = bpack(h0, h1);
            hp[lane*2 + 1] = bpack(h2, h3);
            lp[lane*2]     = bpack(l0, l1);
            lp[lane*2 + 1] = bpack(l2, l3);
        }
        __syncthreads();

        // ---- tensor-core GEMM: 8 k-steps x 8 n-tiles x 3 split mmas ----
        float Cacc[8][4];
        #pragma unroll
        for (int nt = 0; nt < 8; nt++)
            #pragma unroll
            for (int q = 0; q < 4; q++) Cacc[nt][q] = 0.f;

        #pragma unroll
        for (int k0 = 0; k0 < 128; k0 += 16) {
            const __nv_bfloat16* xh = xhi + (r0 + fr)*XS_ + k0 + fc;
            const __nv_bfloat16* xl = xlo + (r0 + fr)*XS_ + k0 + fc;
            unsigned ah0 = *(const unsigned*)(xh);
            unsigned ah1 = *(const unsigned*)(xh + 8*XS_);
            unsigned ah2 = *(const unsigned*)(xh + 8);
            unsigned ah3 = *(const unsigned*)(xh + 8*XS_ + 8);
            unsigned al0 = *(const unsigned*)(xl);
            unsigned al1 = *(const unsigned*)(xl + 8*XS_);
            unsigned al2 = *(const unsigned*)(xl + 8);
            unsigned al3 = *(const unsigned*)(xl + 8*XS_ + 8);
            #pragma unroll
            for (int nt = 0; nt < 8; nt++) {
                const int n0 = ch*64 + nt*8;
                const __nv_bfloat16* wh = WThi + (n0 + fr)*XS_ + k0 + fc;
                const __nv_bfloat16* wl = WTlo + (n0 + fr)*XS_ + k0 + fc;
                unsigned bh0 = *(const unsigned*)(wh);
                unsigned bh1 = *(const unsigned*)(wh + 8);
                unsigned bl0 = *(const unsigned*)(wl);
                unsigned bl1 = *(const unsigned*)(wl + 8);
                mma16816(Cacc[nt], ah0, ah1, ah2, ah3, bh0, bh1);
                mma16816(Cacc[nt], ah0, ah1, ah2, ah3, bl0, bl1);
                mma16816(Cacc[nt], al0, al1, al2, al3, bh0, bh1);
            }
        }
        __syncthreads();   // all fragment reads done -> reuse x region

        // ---- epilogue: C fragments -> staging ----
        if (ch == 0) {
            #pragma unroll
            for (int nt = 0; nt < 8; nt++) {
                int col = nt*8 + fc;
                int row = r0 + fr;
                kstage[col*68 + row]         = Cacc[nt][0];
                kstage[(col+1)*68 + row]     = Cacc[nt][1];
                kstage[col*68 + row + 8]     = Cacc[nt][2];
                kstage[(col+1)*68 + row + 8] = Cacc[nt][3];
            }
        } else {
            #pragma unroll
            for (int nt = 0; nt < 8; nt++) {
                int vc = nt*8 + fc;
                int row = r0 + fr;
                *(float2*)(vstage + row*66 + vc) =
                    make_float2(Cacc[nt][0], Cacc[nt][1]);
                *(float2*)(vstage + (row+8)*66 + vc) =
                    make_float2(Cacc[nt][2], Cacc[nt][3]);
            }
        }
        __syncthreads();

        // ---- coalesced global stores ----
        {
            const size_t bb2 = (size_t)(row0 >> 12);
            const int jj0 = row0 & 4095;
            #pragma unroll 4
            for (int idx = tid; idx < 4096; idx += 256) {
                int col = idx >> 6, j = idx & 63;
                g_kT[(bb2*64 + col)*4096 + jj0 + j] = kstage[col*68 + j];
            }
            #pragma unroll 2
            for (int idx = tid; idx < 2048; idx += 256) {
                int row = idx >> 5, dq = (idx & 31) * 2;
                *(float2*)(g_v + (size_t)(row0 + row)*64 + dq) =
                    *(float2*)(vstage + row*66 + dq);
            }
        }
        __syncthreads();   // before next tile's LN overwrites staging/x
    }
}

// ---------------------------------------------------------------------------
// FUSED iteration kernel (cooperative) — byte-identical to R14 (known-good).
// ---------------------------------------------------------------------------
__global__ void __launch_bounds__(256, 4)
fused_iter_kernel(
    const float* __restrict__ slot,
    const float* __restrict__ qg,   const float* __restrict__ qb,
    const float* __restrict__ Wq,
    const float* __restrict__ qbgg, const float* __restrict__ qbgb,
    const float* __restrict__ Wqbg,
    const float* __restrict__ gwih, const float* __restrict__ gwhh,
    const float* __restrict__ gbih, const float* __restrict__ gbhh,
    const float* __restrict__ bgwih, const float* __restrict__ bgwhh,
    const float* __restrict__ bgbih, const float* __restrict__ bgbhh,
    const float* __restrict__ rlng, const float* __restrict__ rlnb,
    const float* __restrict__ rw1,  const float* __restrict__ rb1,
    const float* __restrict__ rw2,  const float* __restrict__ rb2,
    const float* __restrict__ bglng, const float* __restrict__ bglnb,
    const float* __restrict__ bgw1,  const float* __restrict__ bgb1,
    const float* __restrict__ bgw2,  const float* __restrict__ bgb2,
    float* __restrict__ out_slots,
    float* __restrict__ out_attn) {
    cg::grid_group grid = cg::this_grid();
    const int bid = blockIdx.x;
    const int t   = threadIdx.x;

    __shared__ float ash[8][256];
    __shared__ unsigned long long qp[4][64];
    __shared__ float xn[64];
    __shared__ float ps[4], ps2[4];
    __shared__ float vecs[2][64], ssh[64], gsh[6][64], hb[128], po[2][64];

    // ================= pre-loop =================
    if (bid < 256) {
        const int r = bid;
        const bool bgr = (r & 7) == 0;
        float x = 0.f;
        if (t < 64) {
            x = slot[r*64 + t];
            float s = x, s2 = x*x;
            #pragma unroll
            for (int o = 16; o > 0; o >>= 1) {
                s  += __shfl_xor_sync(0xffffffffu, s,  o);
                s2 += __shfl_xor_sync(0xffffffffu, s2, o);
            }
            if ((t & 31) == 0) { ps[t>>5] = s; ps2[t>>5] = s2; }
        }
        __syncthreads();
        if (t < 64) {
            const float* g  = bgr ? qbgg : qg;
            const float* bt = bgr ? qbgb : qb;
            float s = ps[0] + ps[1], s2 = ps2[0] + ps2[1];
            float mean = s * (1.f/64.f);
            float var  = s2 * (1.f/64.f) - mean*mean;
            float rstd = rsqrtf(var + 1e-5f);
            xn[t] = (x - mean)*rstd*g[t] + bt[t];
        }
        __syncthreads();
        if (t < 64) {
            const float* W = bgr ? Wqbg : Wq;
            float a0 = 0.f, a1 = 0.f;
            #pragma unroll 8
            for (int c = 0; c < 64; c += 2) {
                a0 += xn[c]  *__ldg(W + c*64 + t);
                a1 += xn[c+1]*__ldg(W + (c+1)*64 + t);
            }
            g_q[r*64 + t] = (a0 + a1) * 0.125f;
            g_upd[r*64 + t] = 0.f;
        }
        if (t == 0) g_sums[r] = 0.f;
    } else if (bid < 268) {
        const int m = (bid - 256) / 3;
        const int p = (bid - 256) % 3;
        const float* src = (m == 0) ? gwih : (m == 1) ? gwhh
                         : (m == 2) ? bgwih : bgwhh;
        for (int i = t; i < 4096; i += 256) {
            int rr = i >> 6, cc = i & 63;
            g_wT[m][(p*64 + cc)*64 + rr] = src[(p*64 + rr)*64 + cc];
        }
    }

    // ================= iteration loop =================
    for (int it = 0; it < 3; it++) {
        grid.sync();

        // ---------------- attn (all 512 blocks) ----------------
        {
            const int b  = bid >> 4;
            const int j0 = (bid & 15) * 256;
            {
                int p = t >> 6, c = t & 63;
                float lo = g_q[b*512 + (2*p)*64 + c];
                float hi = g_q[b*512 + (2*p+1)*64 + c];
                qp[p][c] = packab(lo, hi);
            }
            __syncthreads();

            const float* kTb = g_kT + (size_t)(b*64)*4096 + j0 + t;
            unsigned long long dp[4] = {0ULL, 0ULL, 0ULL, 0ULL};
            #pragma unroll 8
            for (int c = 0; c < 64; c++) {
                unsigned long long kc = pack2(__ldg(kTb + (size_t)c*4096));
                dp[0] = fma2(kc, qp[0][c], dp[0]);
                dp[1] = fma2(kc, qp[1][c], dp[1]);
                dp[2] = fma2(kc, qp[2][c], dp[2]);
                dp[3] = fma2(kc, qp[3][c], dp[3]);
            }
            float dots[8];
            #pragma unroll
            for (int p = 0; p < 4; p++) {
                float2 d2 = unpack2(dp[p]);
                dots[2*p]   = d2.x;
                dots[2*p+1] = d2.y;
            }
            float mx = -1e30f;
            #pragma unroll
            for (int i = 0; i < 8; i++) mx = fmaxf(mx, dots[i]);
            float e[8], se = 0.f;
            #pragma unroll
            for (int i = 0; i < 8; i++) { e[i] = __expf(dots[i] - mx); se += e[i]; }
            float inv = 1.f / se;
            #pragma unroll
            for (int i = 0; i < 8; i++) {
                float a = e[i]*inv + 1e-8f;
                ash[i][t] = a;
                if (it == 2)
                    out_attn[((size_t)(b*8 + i))*N_ + j0 + t] = a;
            }
            __syncthreads();

            {
                int w = t >> 5, lane = t & 31;
                float s = 0.f;
                #pragma unroll
                for (int q8 = 0; q8 < 8; q8++) s += ash[w][lane + 32*q8];
                #pragma unroll
                for (int o = 16; o > 0; o >>= 1)
                    s += __shfl_xor_sync(0xffffffffu, s, o);
                if (lane == 0) atomicAdd(&g_sums[b*8 + w], s);
            }

            // phase 2: v read exactly once per block
            {
                const int d4   = t & 15;
                const int quad = (t >> 4) & 1;
                const int jw   = (t >> 5) * 32;
                float4 up0 = make_float4(0.f,0.f,0.f,0.f);
                float4 up1 = up0, up2 = up0, up3 = up0;
                const float4* vp =
                    (const float4*)(g_v + ((size_t)b*N_ + j0 + jw)*64);
                const float* a0p = &ash[quad*4 + 0][jw];
                const float* a1p = &ash[quad*4 + 1][jw];
                const float* a2p = &ash[quad*4 + 2][jw];
                const float* a3p = &ash[quad*4 + 3][jw];
                #pragma unroll 4
                for (int j = 0; j < 32; j++) {
                    float4 vv = __ldg(vp + j*16 + d4);
                    float a0 = a0p[j], a1 = a1p[j], a2 = a2p[j], a3 = a3p[j];
                    up0.x += a0*vv.x; up0.y += a0*vv.y;
                    up0.z += a0*vv.z; up0.w += a0*vv.w;
                    up1.x += a1*vv.x; up1.y += a1*vv.y;
                    up1.z += a1*vv.z; up1.w += a1*vv.w;
                    up2.x += a2*vv.x; up2.y += a2*vv.y;
                    up2.z += a2*vv.z; up2.w += a2*vv.w;
                    up3.x += a3*vv.x; up3.y += a3*vv.y;
                    up3.z += a3*vv.z; up3.w += a3*vv.w;
                }
                float* ub = &g_upd[((size_t)(b*8) + quad*4)*64 + d4*4];
                atomicAdd(ub+0,      up0.x); atomicAdd(ub+1,      up0.y);
                atomicAdd(ub+2,      up0.z); atomicAdd(ub+3,      up0.w);
                atomicAdd(ub+64+0,   up1.x); atomicAdd(ub+64+1,   up1.y);
                atomicAdd(ub+64+2,   up1.z); atomicAdd(ub+64+3,   up1.w);
                atomicAdd(ub+128+0,  up2.x); atomicAdd(ub+128+1,  up2.y);
                atomicAdd(ub+128+2,  up2.z); atomicAdd(ub+128+3,  up2.w);
                atomicAdd(ub+192+0,  up3.x); atomicAdd(ub+192+1,  up3.y);
                atomicAdd(ub+192+2,  up3.z); atomicAdd(ub+192+3,  up3.w);
            }
        }

        grid.sync();

        // ---------------- update (blocks 0..255) ----------------
        if (bid < 256) {
            const int r    = bid;
            const int half = t >> 6;
            const int u    = t & 63;
            const bool bgr = (r & 7) == 0;
            const float* sp = (it == 0) ? slot : (const float*)g_slot;

            if (half == 0)      vecs[0][u] = g_upd[r*64 + u] / g_sums[r];
            else if (half == 1) vecs[1][u] = sp[r*64 + u];
            __syncthreads();

            if (half < 2) {
                const float* wT   = (half == 0) ? (bgr ? g_wT[2] : g_wT[0])
                                                : (bgr ? g_wT[3] : g_wT[1]);
                const float* bias = (half == 0) ? (bgr ? bgbih : gbih)
                                                : (bgr ? bgbhh : gbhh);
                const float* vec  = vecs[half];
                #pragma unroll
                for (int p = 0; p < 3; p++) {
                    const float* wp = wT + (size_t)(p*64)*64 + u;
                    float a0 = 0.f, a1 = 0.f, a2 = 0.f, a3 = 0.f;
                    #pragma unroll
                    for (int c = 0; c < 64; c += 4) {
                        a0 += vec[c]  *__ldg(wp + (size_t)(c  )*64);
                        a1 += vec[c+1]*__ldg(wp + (size_t)(c+1)*64);
                        a2 += vec[c+2]*__ldg(wp + (size_t)(c+2)*64);
                        a3 += vec[c+3]*__ldg(wp + (size_t)(c+3)*64);
                    }
                    gsh[half*3 + p][u] = (a0 + a1) + (a2 + a3) + bias[p*64 + u];
                }
            }
            __syncthreads();

            float s = 0.f;
            if (t < 64) {
                float hval = vecs[1][u];
                float rg = 1.f/(1.f + __expf(-(gsh[0][u] + gsh[3][u])));
                float z  = 1.f/(1.f + __expf(-(gsh[1][u] + gsh[4][u])));
                float n  = tanhf(gsh[2][u] + rg*gsh[5][u]);
                s = (1.f - z)*n + z*hval;
                ssh[u] = s;
                float a = s, a2v = s*s;
                #pragma unroll
                for (int o = 16; o > 0; o >>= 1) {
                    a   += __shfl_xor_sync(0xffffffffu, a,   o);
                    a2v += __shfl_xor_sync(0xffffffffu, a2v, o);
                }
                if ((t & 31) == 0) { ps[t>>5] = a; ps2[t>>5] = a2v; }
            }
            __syncthreads();
            if (t < 64) {
                const float* lng = bgr ? bglng : rlng;
                const float* lnb = bgr ? bglnb : rlnb;
                float tot = ps[0] + ps[1], tot2 = ps2[0] + ps2[1];
                float mean = tot * (1.f/64.f);
                float var  = tot2 * (1.f/64.f) - mean*mean;
                float rstd = rsqrtf(var + 1e-5f);
                xn[u] = (s - mean)*rstd*lng[u] + lnb[u];
            }
            __syncthreads();

            if (t < 128) {
                const float* w1 = bgr ? bgw1 : rw1;
                const float* b1 = bgr ? bgb1 : rb1;
                float h0 = b1[t], h1 = 0.f, h2 = 0.f, h3 = 0.f;
                #pragma unroll
                for (int c = 0; c < 64; c += 4) {
                    h0 += xn[c]  *__ldg(w1 + (c  )*128 + t);
                    h1 += xn[c+1]*__ldg(w1 + (c+1)*128 + t);
                    h2 += xn[c+2]*__ldg(w1 + (c+2)*128 + t);
                    h3 += xn[c+3]*__ldg(w1 + (c+3)*128 + t);
                }
                hb[t] = fmaxf((h0 + h1) + (h2 + h3), 0.f);
            }
            __syncthreads();

            if (half < 2) {
                const float* w2 = bgr ? bgw2 : rw2;
                float o0 = 0.f, o1 = 0.f, o2 = 0.f, o3 = 0.f;
                const int hh0 = half * 64;
                #pragma unroll
                for (int hh = 0; hh < 64; hh += 4) {
                    o0 += hb[hh0+hh]  *__ldg(w2 + (hh0+hh  )*64 + u);
                    o1 += hb[hh0+hh+1]*__ldg(w2 + (hh0+hh+1)*64 + u);
                    o2 += hb[hh0+hh+2]*__ldg(w2 + (hh0+hh+2)*64 + u);
                    o3 += hb[hh0+hh+3]*__ldg(w2 + (hh0+hh+3)*64 + u);
                }
                po[half][u] = (o0 + o1) + (o2 + o3);
            }
            __syncthreads();

            float o = 0.f;
            if (t < 64) {
                const float* b2 = bgr ? bgb2 : rb2;
                o = ssh[u] + b2[u] + po[0][u] + po[1][u];
                g_slot[r*64 + u] = o;
                if (it == 2) out_slots[r*64 + u] = o;
            }

            if (it < 2) {
                if (t < 64) {
                    float a = o, a2v = o*o;
                    #pragma unroll
                    for (int off = 16; off > 0; off >>= 1) {
                        a   += __shfl_xor_sync(0xffffffffu, a,   off);
                        a2v += __shfl_xor_sync(0xffffffffu, a2v, off);
                    }
                    if ((t & 31) == 0) { ps[t>>5] = a; ps2[t>>5] = a2v; }
                }
                __syncthreads();
                if (t < 64) {
                    const float* qgp = bgr ? qbgg : qg;
                    const float* qbp = bgr ? qbgb : qb;
                    float tot = ps[0] + ps[1], tot2 = ps2[0] + ps2[1];
                    float mean = tot * (1.f/64.f);
                    float var  = tot2 * (1.f/64.f) - mean*mean;
                    float rstd = rsqrtf(var + 1e-5f);
                    xn[u] = (o - mean)*rstd*qgp[u] + qbp[u];
                }
                __syncthreads();
                if (half < 2) {
                    const float* Wp = bgr ? Wqbg : Wq;
                    const int c0 = half * 32;
                    float q0 = 0.f, q1 = 0.f;
                    #pragma unroll
                    for (int c = 0; c < 32; c += 2) {
                        q0 += xn[c0+c]  *__ldg(Wp + (c0+c  )*64 + u);
                        q1 += xn[c0+c+1]*__ldg(Wp + (c0+c+1)*64 + u);
                    }
                    po[half][u] = q0 + q1;
                }
                __syncthreads();
                if (t < 64) {
                    g_q[r*64 + u] = (po[0][u] + po[1][u]) * 0.125f;
                    g_upd[r*64 + u] = 0.f;
                }
                if (t == 0) g_sums[r] = 0.f;
            }
        }
    }
}

// ---------------------------------------------------------------------------
extern "C" void kernel_launch(void* const* d_in, const int* in_sizes, int n_in,
                              void* d_out, int out_size) {
    const float* feat   = (const float*)d_in[0];
    const float* slot   = (const float*)d_in[1];
    const float* nfg    = (const float*)d_in[2];
    const float* nfb    = (const float*)d_in[3];
    const float* Wk     = (const float*)d_in[4];
    const float* Wv     = (const float*)d_in[5];
    const float* qg     = (const float*)d_in[6];
    const float* qb     = (const float*)d_in[7];
    const float* Wq     = (const float*)d_in[8];
    const float* qbgg   = (const float*)d_in[9];
    const float* qbgb   = (const float*)d_in[10];
    const float* Wqbg   = (const float*)d_in[11];
    const float* gwih   = (const float*)d_in[12];
    const float* gwhh   = (const float*)d_in[13];
    const float* gbih   = (const float*)d_in[14];
    const float* gbhh   = (const float*)d_in[15];
    const float* bgwih  = (const float*)d_in[16];
    const float* bgwhh  = (const float*)d_in[17];
    const float* bgbih  = (const float*)d_in[18];
    const float* bgbhh  = (const float*)d_in[19];
    const float* rlng   = (const float*)d_in[20];
    const float* rlnb   = (const float*)d_in[21];
    const float* rw1    = (const float*)d_in[22];
    const float* rb1    = (const float*)d_in[23];
    const float* rw2    = (const float*)d_in[24];
    const float* rb2    = (const float*)d_in[25];
    const float* bglng  = (const float*)d_in[26];
    const float* bglnb  = (const float*)d_in[27];
    const float* bgw1   = (const float*)d_in[28];
    const float* bgb1   = (const float*)d_in[29];
    const float* bgw2   = (const float*)d_in[30];
    const float* bgb2   = (const float*)d_in[31];

    float* out       = (float*)d_out;
    float* out_attn  = out + SLOTS_*D_;   // slots first, then attn

    // xhi|xlo (64*XS_*2 each) + WThi|WTlo (128*XS_*2 each) = 104448 B
    const int smem_lnkv = (64*XS_*2)*2 + (128*XS_*2)*2;
    cudaFuncSetAttribute(ln_kv_kernel,
                         cudaFuncAttributeMaxDynamicSharedMemorySize, smem_lnkv);

    ln_kv_kernel<<<296, 256, smem_lnkv>>>(feat, nfg, nfb, Wk, Wv);

    void* args[] = {
        (void*)&slot,
        (void*)&qg,   (void*)&qb,   (void*)&Wq,
        (void*)&qbgg, (void*)&qbgb, (void*)&Wqbg,
        (void*)&gwih, (void*)&gwhh, (void*)&gbih, (void*)&gbhh,
        (void*)&bgwih, (void*)&bgwhh, (void*)&bgbih, (void*)&bgbhh,
        (void*)&rlng, (void*)&rlnb, (void*)&rw1, (void*)&rb1,
        (void*)&rw2,  (void*)&rb2,
        (void*)&bglng, (void*)&bglnb, (void*)&bgw1, (void*)&bgb1,
        (void*)&bgw2,  (void*)&bgb2,
        (void*)&out, (void*)&out_attn
    };
    cudaLaunchCooperativeKernel((const void*)fused_iter_kernel,
                                dim3(512), dim3(256), args, 0, (cudaStream_t)0);
}

// round 17
// speedup vs baseline: 1.5841x; 1.0357x over previous
#include <cuda_runtime.h>
#include <cooperative_groups.h>
#include <cuda_bf16.h>
#include <math.h>

namespace cg = cooperative_groups;

// Shapes
#define B_   32
#define N_   4096
#define C_   128
#define D_   64
#define K_   8
#define H_   128
#define BN_  (B_*N_)          // 131072
#define SLOTS_ (B_*K_)        // 256

// Scratch (device globals; no allocation allowed)
__device__ float g_kT[B_*D_*N_];   // transposed k: [b][d][j]
__device__ float g_v[BN_*D_];
__device__ float g_q[SLOTS_*D_];
__device__ float g_upd[SLOTS_*D_];
__device__ float g_sums[SLOTS_];
__device__ float g_slot[SLOTS_*D_];
__device__ float g_wT[4][192*64];
__device__ int   g_done[B_][3];

// ---- packed f32x2 helpers (Blackwell FFMA2) --------------------------------
__device__ __forceinline__ unsigned long long pack2(float x) {
    unsigned long long r;
    unsigned xi = __float_as_uint(x);
    asm("mov.b64 %0, {%1, %1};" : "=l"(r) : "r"(xi));
    return r;
}
__device__ __forceinline__ unsigned long long packab(float lo, float hi) {
    unsigned long long r;
    asm("mov.b64 %0, {%1, %2};" : "=l"(r)
        : "r"(__float_as_uint(lo)), "r"(__float_as_uint(hi)));
    return r;
}
__device__ __forceinline__ unsigned long long fma2(unsigned long long a,
                                                   unsigned long long b,
                                                   unsigned long long c) {
    unsigned long long d;
    asm("fma.rn.f32x2 %0, %1, %2, %3;" : "=l"(d) : "l"(a), "l"(b), "l"(c));
    return d;
}
__device__ __forceinline__ float2 unpack2(unsigned long long v) {
    unsigned lo, hi;
    asm("mov.b64 {%0, %1}, %2;" : "=r"(lo), "=r"(hi) : "l"(v));
    float2 f; f.x = __uint_as_float(lo); f.y = __uint_as_float(hi);
    return f;
}

// ---- mma.sync bf16 helper (sm_80+ path; compiles for sm_103) ---------------
__device__ __forceinline__ void mma16816(float c[4],
                                         unsigned a0, unsigned a1,
                                         unsigned a2, unsigned a3,
                                         unsigned b0, unsigned b1) {
    asm volatile(
        "mma.sync.aligned.m16n8k16.row.col.f32.bf16.bf16.f32 "
        "{%0,%1,%2,%3}, {%4,%5,%6,%7}, {%8,%9}, {%0,%1,%2,%3};"
        : "+f"(c[0]), "+f"(c[1]), "+f"(c[2]), "+f"(c[3])
        : "r"(a0), "r"(a1), "r"(a2), "r"(a3), "r"(b0), "r"(b1));
}
__device__ __forceinline__ unsigned bpack(__nv_bfloat16 a, __nv_bfloat16 b) {
    return ((unsigned)__bfloat16_as_ushort(b) << 16) | __bfloat16_as_ushort(a);
}

// ---------------------------------------------------------------------------
// Kernel A (R16 known-good, tensor-core): LN + bf16-split mma.sync GEMM.
// ---------------------------------------------------------------------------
#define XS_ 136
__global__ void __launch_bounds__(256)
ln_kv_kernel(const float* __restrict__ feat,
             const float* __restrict__ gamma,
             const float* __restrict__ beta,
             const float* __restrict__ Wk,
             const float* __restrict__ Wv) {
    extern __shared__ char smraw[];
    __nv_bfloat16* xhi  = (__nv_bfloat16*)smraw;            // 64 x XS_
    __nv_bfloat16* xlo  = xhi + 64*XS_;
    __nv_bfloat16* WThi = xlo + 64*XS_;                     // 128 outs x XS_
    __nv_bfloat16* WTlo = WThi + 128*XS_;
    float* kstage = (float*)smraw;                          // reuse x region
    float* vstage = kstage + 64*68;

    const int tid  = threadIdx.x;
    const int lane = tid & 31;
    const int warp = tid >> 5;

    for (int idx = tid; idx < 128*64; idx += 256) {
        int c = idx >> 6, o = idx & 63;
        float wk = Wk[idx], wv = Wv[idx];
        __nv_bfloat16 h = __float2bfloat16(wk);
        WThi[o*XS_ + c] = h;
        WTlo[o*XS_ + c] = __float2bfloat16(wk - __bfloat162float(h));
        h = __float2bfloat16(wv);
        WThi[(64 + o)*XS_ + c] = h;
        WTlo[(64 + o)*XS_ + c] = __float2bfloat16(wv - __bfloat162float(h));
    }
    const float4 gg = ((const float4*)gamma)[lane];
    const float4 bb = ((const float4*)beta)[lane];
    __syncthreads();

    const int r0 = (warp & 3) * 16;
    const int ch = warp >> 2;
    const int fr = lane >> 2;
    const int fc = (lane & 3) * 2;

    for (int chunk = blockIdx.x; chunk < BN_/64; chunk += gridDim.x) {
        const int row0 = chunk * 64;
        #pragma unroll
        for (int rr = 0; rr < 8; rr++) {
            int rl = warp*8 + rr;
            float4 xv = ((const float4*)(feat + (size_t)(row0+rl)*128))[lane];
            float s  = xv.x+xv.y+xv.z+xv.w;
            float s2 = xv.x*xv.x + xv.y*xv.y + xv.z*xv.z + xv.w*xv.w;
            #pragma unroll
            for (int o = 16; o > 0; o >>= 1) {
                s  += __shfl_xor_sync(0xffffffffu, s,  o);
                s2 += __shfl_xor_sync(0xffffffffu, s2, o);
            }
            float mean = s * (1.f/128.f);
            float var  = s2 * (1.f/128.f) - mean*mean;
            float rstd = rsqrtf(var + 1e-5f);
            float x0 = (xv.x-mean)*rstd*gg.x + bb.x;
            float x1 = (xv.y-mean)*rstd*gg.y + bb.y;
            float x2 = (xv.z-mean)*rstd*gg.z + bb.z;
            float x3 = (xv.w-mean)*rstd*gg.w + bb.w;
            __nv_bfloat16 h0 = __float2bfloat16(x0);
            __nv_bfloat16 h1 = __float2bfloat16(x1);
            __nv_bfloat16 h2 = __float2bfloat16(x2);
            __nv_bfloat16 h3 = __float2bfloat16(x3);
            __nv_bfloat16 l0 = __float2bfloat16(x0 - __bfloat162float(h0));
            __nv_bfloat16 l1 = __float2bfloat16(x1 - __bfloat162float(h1));
            __nv_bfloat16 l2 = __float2bfloat16(x2 - __bfloat162float(h2));
            __nv_bfloat16 l3 = __float2bfloat16(x3 - __bfloat162float(h3));
            unsigned* hp = (unsigned*)(xhi + rl*XS_);
            unsigned* lp = (unsigned*)(xlo + rl*XS_);
            hp[lane*2]     = bpack(h0, h1);
            hp[lane*2 + 1] = bpack(h2, h3);
            lp[lane*2]     = bpack(l0, l1);
            lp[lane*2 + 1] = bpack(l2, l3);
        }
        __syncthreads();

        float Cacc[8][4];
        #pragma unroll
        for (int nt = 0; nt < 8; nt++)
            #pragma unroll
            for (int q = 0; q < 4; q++) Cacc[nt][q] = 0.f;

        #pragma unroll
        for (int k0 = 0; k0 < 128; k0 += 16) {
            const __nv_bfloat16* xh = xhi + (r0 + fr)*XS_ + k0 + fc;
            const __nv_bfloat16* xl = xlo + (r0 + fr)*XS_ + k0 + fc;
            unsigned ah0 = *(const unsigned*)(xh);
            unsigned ah1 = *(const unsigned*)(xh + 8*XS_);
            unsigned ah2 = *(const unsigned*)(xh + 8);
            unsigned ah3 = *(const unsigned*)(xh + 8*XS_ + 8);
            unsigned al0 = *(const unsigned*)(xl);
            unsigned al1 = *(const unsigned*)(xl + 8*XS_);
            unsigned al2 = *(const unsigned*)(xl + 8);
            unsigned al3 = *(const unsigned*)(xl + 8*XS_ + 8);
            #pragma unroll
            for (int nt = 0; nt < 8; nt++) {
                const int n0 = ch*64 + nt*8;
                const __nv_bfloat16* wh = WThi + (n0 + fr)*XS_ + k0 + fc;
                const __nv_bfloat16* wl = WTlo + (n0 + fr)*XS_ + k0 + fc;
                unsigned bh0 = *(const unsigned*)(wh);
                unsigned bh1 = *(const unsigned*)(wh + 8);
                unsigned bl0 = *(const unsigned*)(wl);
                unsigned bl1 = *(const unsigned*)(wl + 8);
                mma16816(Cacc[nt], ah0, ah1, ah2, ah3, bh0, bh1);
                mma16816(Cacc[nt], ah0, ah1, ah2, ah3, bl0, bl1);
                mma16816(Cacc[nt], al0, al1, al2, al3, bh0, bh1);
            }
        }
        __syncthreads();

        if (ch == 0) {
            #pragma unroll
            for (int nt = 0; nt < 8; nt++) {
                int col = nt*8 + fc;
                int row = r0 + fr;
                kstage[col*68 + row]         = Cacc[nt][0];
                kstage[(col+1)*68 + row]     = Cacc[nt][1];
                kstage[col*68 + row + 8]     = Cacc[nt][2];
                kstage[(col+1)*68 + row + 8] = Cacc[nt][3];
            }
        } else {
            #pragma unroll
            for (int nt = 0; nt < 8; nt++) {
                int vc = nt*8 + fc;
                int row = r0 + fr;
                *(float2*)(vstage + row*66 + vc) =
                    make_float2(Cacc[nt][0], Cacc[nt][1]);
                *(float2*)(vstage + (row+8)*66 + vc) =
                    make_float2(Cacc[nt][2], Cacc[nt][3]);
            }
        }
        __syncthreads();

        {
            const size_t bb2 = (size_t)(row0 >> 12);
            const int jj0 = row0 & 4095;
            #pragma unroll 4
            for (int idx = tid; idx < 4096; idx += 256) {
                int col = idx >> 6, j = idx & 63;
                g_kT[(bb2*64 + col)*4096 + jj0 + j] = kstage[col*68 + j];
            }
            #pragma unroll 2
            for (int idx = tid; idx < 2048; idx += 256) {
                int row = idx >> 5, dq = (idx & 31) * 2;
                *(float2*)(g_v + (size_t)(row0 + row)*64 + dq) =
                    *(float2*)(vstage + row*66 + dq);
            }
        }
        __syncthreads();
    }
}

// ---------------------------------------------------------------------------
// FUSED kernel: per-batch counter sync; parallel 8-block update.
// done[b][it]: 16 = all attn blocks done; 24 = all update rows done.
// ---------------------------------------------------------------------------
__global__ void __launch_bounds__(256, 4)
fused_iter_kernel(
    const float* __restrict__ slot,
    const float* __restrict__ qg,   const float* __restrict__ qb,
    const float* __restrict__ Wq,
    const float* __restrict__ qbgg, const float* __restrict__ qbgb,
    const float* __restrict__ Wqbg,
    const float* __restrict__ gwih, const float* __restrict__ gwhh,
    const float* __restrict__ gbih, const float* __restrict__ gbhh,
    const float* __restrict__ bgwih, const float* __restrict__ bgwhh,
    const float* __restrict__ bgbih, const float* __restrict__ bgbhh,
    const float* __restrict__ rlng, const float* __restrict__ rlnb,
    const float* __restrict__ rw1,  const float* __restrict__ rb1,
    const float* __restrict__ rw2,  const float* __restrict__ rb2,
    const float* __restrict__ bglng, const float* __restrict__ bglnb,
    const float* __restrict__ bgw1,  const float* __restrict__ bgb1,
    const float* __restrict__ bgw2,  const float* __restrict__ bgb2,
    float* __restrict__ out_slots,
    float* __restrict__ out_attn) {
    cg::grid_group grid = cg::this_grid();
    const int bid = blockIdx.x;
    const int t   = threadIdx.x;
    const int b   = bid >> 4;
    const int jb  = bid & 15;
    const int j0  = jb * 256;

    __shared__ float ash[8][256];
    __shared__ unsigned long long qp[4][64];
    __shared__ float xn[64];
    __shared__ float ps[4], ps2[4];
    __shared__ float vecs[2][64], ssh[64], gsh[6][64], hb[128], po[2][64];

    // ================= pre-loop =================
    if (bid < 256) {
        const int r = bid;
        const bool bgr = (r & 7) == 0;
        if (r < 32 && t == 128) {    // zero counters (graph-replay safe)
            g_done[r][0] = 0; g_done[r][1] = 0; g_done[r][2] = 0;
        }
        float x = 0.f;
        if (t < 64) {
            x = slot[r*64 + t];
            float s = x, s2 = x*x;
            #pragma unroll
            for (int o = 16; o > 0; o >>= 1) {
                s  += __shfl_xor_sync(0xffffffffu, s,  o);
                s2 += __shfl_xor_sync(0xffffffffu, s2, o);
            }
            if ((t & 31) == 0) { ps[t>>5] = s; ps2[t>>5] = s2; }
        }
        __syncthreads();
        if (t < 64) {
            const float* g  = bgr ? qbgg : qg;
            const float* bt = bgr ? qbgb : qb;
            float s = ps[0] + ps[1], s2 = ps2[0] + ps2[1];
            float mean = s * (1.f/64.f);
            float var  = s2 * (1.f/64.f) - mean*mean;
            float rstd = rsqrtf(var + 1e-5f);
            xn[t] = (x - mean)*rstd*g[t] + bt[t];
        }
        __syncthreads();
        if (t < 64) {
            const float* W = bgr ? Wqbg : Wq;
            float a0 = 0.f, a1 = 0.f;
            #pragma unroll 8
            for (int c = 0; c < 64; c += 2) {
                a0 += xn[c]  *__ldg(W + c*64 + t);
                a1 += xn[c+1]*__ldg(W + (c+1)*64 + t);
            }
            g_q[r*64 + t] = (a0 + a1) * 0.125f;
            g_upd[r*64 + t] = 0.f;
        }
        if (t == 0) g_sums[r] = 0.f;
    } else if (bid < 268) {
        const int m = (bid - 256) / 3;
        const int p = (bid - 256) % 3;
        const float* src = (m == 0) ? gwih : (m == 1) ? gwhh
                         : (m == 2) ? bgwih : bgwhh;
        for (int i = t; i < 4096; i += 256) {
            int rr = i >> 6, cc = i & 63;
            g_wT[m][(p*64 + cc)*64 + rr] = src[(p*64 + rr)*64 + cc];
        }
    }

    grid.sync();   // the ONLY grid-wide barrier

    // ================= per-batch dataflow loop =================
    for (int it = 0; it < 3; it++) {
        // gate: all 8 update rows of previous iteration done (24 arrivals)
        if (it > 0) {
            if (t == 0) {
                while (*(volatile int*)&g_done[b][it-1] < 24) __nanosleep(64);
                __threadfence();   // invalidate L1: fresh g_q/g_slot
            }
            __syncthreads();
        }

        // ---------------- attn ----------------
        {
            int p = t >> 6, c = t & 63;
            float lo = g_q[b*512 + (2*p)*64 + c];
            float hi = g_q[b*512 + (2*p+1)*64 + c];
            qp[p][c] = packab(lo, hi);
        }
        __syncthreads();

        const float* kTb = g_kT + (size_t)(b*64)*4096 + j0 + t;
        unsigned long long dp[4] = {0ULL, 0ULL, 0ULL, 0ULL};
        #pragma unroll 8
        for (int c = 0; c < 64; c++) {
            unsigned long long kc = pack2(__ldg(kTb + (size_t)c*4096));
            dp[0] = fma2(kc, qp[0][c], dp[0]);
            dp[1] = fma2(kc, qp[1][c], dp[1]);
            dp[2] = fma2(kc, qp[2][c], dp[2]);
            dp[3] = fma2(kc, qp[3][c], dp[3]);
        }
        float dots[8];
        #pragma unroll
        for (int p = 0; p < 4; p++) {
            float2 d2 = unpack2(dp[p]);
            dots[2*p]   = d2.x;
            dots[2*p+1] = d2.y;
        }
        float mx = -1e30f;
        #pragma unroll
        for (int i = 0; i < 8; i++) mx = fmaxf(mx, dots[i]);
        float e[8], se = 0.f;
        #pragma unroll
        for (int i = 0; i < 8; i++) { e[i] = __expf(dots[i] - mx); se += e[i]; }
        float inv = 1.f / se;
        #pragma unroll
        for (int i = 0; i < 8; i++) {
            float a = e[i]*inv + 1e-8f;
            ash[i][t] = a;
            if (it == 2)
                out_attn[((size_t)(b*8 + i))*N_ + j0 + t] = a;
        }
        __syncthreads();

        {
            int w = t >> 5, lane = t & 31;
            float s = 0.f;
            #pragma unroll
            for (int q8 = 0; q8 < 8; q8++) s += ash[w][lane + 32*q8];
            #pragma unroll
            for (int o = 16; o > 0; o >>= 1)
                s += __shfl_xor_sync(0xffffffffu, s, o);
            if (lane == 0) atomicAdd(&g_sums[b*8 + w], s);
        }

        // phase 2: v read once per block (R14/R16 mapping)
        {
            const int d4   = t & 15;
            const int quad = (t >> 4) & 1;
            const int jw   = (t >> 5) * 32;
            float4 up0 = make_float4(0.f,0.f,0.f,0.f);
            float4 up1 = up0, up2 = up0, up3 = up0;
            const float4* vp =
                (const float4*)(g_v + ((size_t)b*N_ + j0 + jw)*64);
            const float* a0p = &ash[quad*4 + 0][jw];
            const float* a1p = &ash[quad*4 + 1][jw];
            const float* a2p = &ash[quad*4 + 2][jw];
            const float* a3p = &ash[quad*4 + 3][jw];
            #pragma unroll 4
            for (int j = 0; j < 32; j++) {
                float4 vv = __ldg(vp + j*16 + d4);
                float a0 = a0p[j], a1 = a1p[j], a2 = a2p[j], a3 = a3p[j];
                up0.x += a0*vv.x; up0.y += a0*vv.y;
                up0.z += a0*vv.z; up0.w += a0*vv.w;
                up1.x += a1*vv.x; up1.y += a1*vv.y;
                up1.z += a1*vv.z; up1.w += a1*vv.w;
                up2.x += a2*vv.x; up2.y += a2*vv.y;
                up2.z += a2*vv.z; up2.w += a2*vv.w;
                up3.x += a3*vv.x; up3.y += a3*vv.y;
                up3.z += a3*vv.z; up3.w += a3*vv.w;
            }
            float* ub = &g_upd[((size_t)(b*8) + quad*4)*64 + d4*4];
            atomicAdd(ub+0,      up0.x); atomicAdd(ub+1,      up0.y);
            atomicAdd(ub+2,      up0.z); atomicAdd(ub+3,      up0.w);
            atomicAdd(ub+64+0,   up1.x); atomicAdd(ub+64+1,   up1.y);
            atomicAdd(ub+64+2,   up1.z); atomicAdd(ub+64+3,   up1.w);
            atomicAdd(ub+128+0,  up2.x); atomicAdd(ub+128+1,  up2.y);
            atomicAdd(ub+128+2,  up2.z); atomicAdd(ub+128+3,  up2.w);
            atomicAdd(ub+192+0,  up3.x); atomicAdd(ub+192+1,  up3.y);
            atomicAdd(ub+192+2,  up3.z); atomicAdd(ub+192+3,  up3.w);
        }

        __threadfence();   // publish my atomics
        __syncthreads();
        if (t == 0) atomicAdd(&g_done[b][it], 1);

        // ---------------- update: blocks jb<8, one row each ----------------
        if (jb < 8) {
            if (t == 0) {
                while (*(volatile int*)&g_done[b][it] < 16) __nanosleep(32);
                __threadfence();   // see all 16 blocks' contributions
            }
            __syncthreads();

            const int r    = b*8 + jb;
            const int half = t >> 6;
            const int u    = t & 63;
            const bool bgr = (jb == 0);
            const float* sp = (it == 0) ? slot : (const float*)g_slot;

            if (half == 0)      vecs[0][u] = g_upd[r*64 + u] / g_sums[r];
            else if (half == 1) vecs[1][u] = sp[r*64 + u];
            __syncthreads();

            if (half < 2) {
                const float* wT   = (half == 0) ? (bgr ? g_wT[2] : g_wT[0])
                                                : (bgr ? g_wT[3] : g_wT[1]);
                const float* bias = (half == 0) ? (bgr ? bgbih : gbih)
                                                : (bgr ? bgbhh : gbhh);
                const float* vec  = vecs[half];
                #pragma unroll
                for (int p = 0; p < 3; p++) {
                    const float* wp = wT + (size_t)(p*64)*64 + u;
                    float a0 = 0.f, a1 = 0.f, a2 = 0.f, a3 = 0.f;
                    #pragma unroll
                    for (int c = 0; c < 64; c += 4) {
                        a0 += vec[c]  *__ldg(wp + (size_t)(c  )*64);
                        a1 += vec[c+1]*__ldg(wp + (size_t)(c+1)*64);
                        a2 += vec[c+2]*__ldg(wp + (size_t)(c+2)*64);
                        a3 += vec[c+3]*__ldg(wp + (size_t)(c+3)*64);
                    }
                    gsh[half*3 + p][u] = (a0 + a1) + (a2 + a3) + bias[p*64 + u];
                }
            }
            __syncthreads();

            float s = 0.f;
            if (t < 64) {
                float hval = vecs[1][u];
                float rg = 1.f/(1.f + __expf(-(gsh[0][u] + gsh[3][u])));
                float z  = 1.f/(1.f + __expf(-(gsh[1][u] + gsh[4][u])));
                float n  = tanhf(gsh[2][u] + rg*gsh[5][u]);
                s = (1.f - z)*n + z*hval;
                ssh[u] = s;
                float a = s, a2v = s*s;
                #pragma unroll
                for (int o = 16; o > 0; o >>= 1) {
                    a   += __shfl_xor_sync(0xffffffffu, a,   o);
                    a2v += __shfl_xor_sync(0xffffffffu, a2v, o);
                }
                if ((t & 31) == 0) { ps[t>>5] = a; ps2[t>>5] = a2v; }
            }
            __syncthreads();
            if (t < 64) {
                const float* lng = bgr ? bglng : rlng;
                const float* lnb = bgr ? bglnb : rlnb;
                float tot = ps[0] + ps[1], tot2 = ps2[0] + ps2[1];
                float mean = tot * (1.f/64.f);
                float var  = tot2 * (1.f/64.f) - mean*mean;
                float rstd = rsqrtf(var + 1e-5f);
                xn[u] = (s - mean)*rstd*lng[u] + lnb[u];
            }
            __syncthreads();

            if (t < 128) {
                const float* w1 = bgr ? bgw1 : rw1;
                const float* b1 = bgr ? bgb1 : rb1;
                float h0 = b1[t], h1 = 0.f, h2 = 0.f, h3 = 0.f;
                #pragma unroll
                for (int c = 0; c < 64; c += 4) {
                    h0 += xn[c]  *__ldg(w1 + (c  )*128 + t);
                    h1 += xn[c+1]*__ldg(w1 + (c+1)*128 + t);
                    h2 += xn[c+2]*__ldg(w1 + (c+2)*128 + t);
                    h3 += xn[c+3]*__ldg(w1 + (c+3)*128 + t);
                }
                hb[t] = fmaxf((h0 + h1) + (h2 + h3), 0.f);
            }
            __syncthreads();

            if (half < 2) {
                const float* w2 = bgr ? bgw2 : rw2;
                float o0 = 0.f, o1 = 0.f, o2 = 0.f, o3 = 0.f;
                const int hh0 = half * 64;
                #pragma unroll
                for (int hh = 0; hh < 64; hh += 4) {
                    o0 += hb[hh0+hh]  *__ldg(w2 + (hh0+hh  )*64 + u);
                    o1 += hb[hh0+hh+1]*__ldg(w2 + (hh0+hh+1)*64 + u);
                    o2 += hb[hh0+hh+2]*__ldg(w2 + (hh0+hh+2)*64 + u);
                    o3 += hb[hh0+hh+3]*__ldg(w2 + (hh0+hh+3)*64 + u);
                }
                po[half][u] = (o0 + o1) + (o2 + o3);
            }
            __syncthreads();

            float o = 0.f;
            if (t < 64) {
                const float* b2 = bgr ? bgb2 : rb2;
                o = ssh[u] + b2[u] + po[0][u] + po[1][u];
                g_slot[r*64 + u] = o;
                if (it == 2) out_slots[r*64 + u] = o;
            }

            if (it < 2) {
                if (t < 64) {
                    float a = o, a2v = o*o;
                    #pragma unroll
                    for (int off = 16; off > 0; off >>= 1) {
                        a   += __shfl_xor_sync(0xffffffffu, a,   off);
                        a2v += __shfl_xor_sync(0xffffffffu, a2v, off);
                    }
                    if ((t & 31) == 0) { ps[t>>5] = a; ps2[t>>5] = a2v; }
                }
                __syncthreads();
                if (t < 64) {
                    const float* qgp = bgr ? qbgg : qg;
                    const float* qbp = bgr ? qbgb : qb;
                    float tot = ps[0] + ps[1], tot2 = ps2[0] + ps2[1];
                    float mean = tot * (1.f/64.f);
                    float var  = tot2 * (1.f/64.f) - mean*mean;
                    float rstd = rsqrtf(var + 1e-5f);
                    xn[u] = (o - mean)*rstd*qgp[u] + qbp[u];
                }
                __syncthreads();
                if (half < 2) {
                    const float* Wp = bgr ? Wqbg : Wq;
                    const int c0 = half * 32;
                    float q0 = 0.f, q1 = 0.f;
                    #pragma unroll
                    for (int c = 0; c < 32; c += 2) {
                        q0 += xn[c0+c]  *__ldg(Wp + (c0+c  )*64 + u);
                        q1 += xn[c0+c+1]*__ldg(Wp + (c0+c+1)*64 + u);
                    }
                    po[half][u] = q0 + q1;
                }
                __syncthreads();
                if (t < 64) {
                    g_q[r*64 + u] = (po[0][u] + po[1][u]) * 0.125f;
                    g_upd[r*64 + u] = 0.f;
                }
                if (t == 0) g_sums[r] = 0.f;

                // publish this row's update (arrival 17..24)
                __threadfence();
                __syncthreads();
                if (t == 0) atomicAdd(&g_done[b][it], 1);
            }
        }
    }
}

// ---------------------------------------------------------------------------
extern "C" void kernel_launch(void* const* d_in, const int* in_sizes, int n_in,
                              void* d_out, int out_size) {
    const float* feat   = (const float*)d_in[0];
    const float* slot   = (const float*)d_in[1];
    const float* nfg    = (const float*)d_in[2];
    const float* nfb    = (const float*)d_in[3];
    const float* Wk     = (const float*)d_in[4];
    const float* Wv     = (const float*)d_in[5];
    const float* qg     = (const float*)d_in[6];
    const float* qb     = (const float*)d_in[7];
    const float* Wq     = (const float*)d_in[8];
    const float* qbgg   = (const float*)d_in[9];
    const float* qbgb   = (const float*)d_in[10];
    const float* Wqbg   = (const float*)d_in[11];
    const float* gwih   = (const float*)d_in[12];
    const float* gwhh   = (const float*)d_in[13];
    const float* gbih   = (const float*)d_in[14];
    const float* gbhh   = (const float*)d_in[15];
    const float* bgwih  = (const float*)d_in[16];
    const float* bgwhh  = (const float*)d_in[17];
    const float* bgbih  = (const float*)d_in[18];
    const float* bgbhh  = (const float*)d_in[19];
    const float* rlng   = (const float*)d_in[20];
    const float* rlnb   = (const float*)d_in[21];
    const float* rw1    = (const float*)d_in[22];
    const float* rb1    = (const float*)d_in[23];
    const float* rw2    = (const float*)d_in[24];
    const float* rb2    = (const float*)d_in[25];
    const float* bglng  = (const float*)d_in[26];
    const float* bglnb  = (const float*)d_in[27];
    const float* bgw1   = (const float*)d_in[28];
    const float* bgb1   = (const float*)d_in[29];
    const float* bgw2   = (const float*)d_in[30];
    const float* bgb2   = (const float*)d_in[31];

    float* out       = (float*)d_out;
    float* out_attn  = out + SLOTS_*D_;   // slots first, then attn

    const int smem_lnkv = (64*XS_*2)*2 + (128*XS_*2)*2;   // 104448 B
    cudaFuncSetAttribute(ln_kv_kernel,
                         cudaFuncAttributeMaxDynamicSharedMemorySize, smem_lnkv);

    ln_kv_kernel<<<296, 256, smem_lnkv>>>(feat, nfg, nfb, Wk, Wv);

    void* args[] = {
        (void*)&slot,
        (void*)&qg,   (void*)&qb,   (void*)&Wq,
        (void*)&qbgg, (void*)&qbgb, (void*)&Wqbg,
        (void*)&gwih, (void*)&gwhh, (void*)&gbih, (void*)&gbhh,
        (void*)&bgwih, (void*)&bgwhh, (void*)&bgbih, (void*)&bgbhh,
        (void*)&rlng, (void*)&rlnb, (void*)&rw1, (void*)&rb1,
        (void*)&rw2,  (void*)&rb2,
        (void*)&bglng, (void*)&bglnb, (void*)&bgw1, (void*)&bgb1,
        (void*)&bgw2,  (void*)&bgb2,
        (void*)&out, (void*)&out_attn
    };
    cudaLaunchCooperativeKernel((const void*)fused_iter_kernel,
                                dim3(512), dim3(256), args, 0, (cudaStream_t)0);
}